// round 2
// baseline (speedup 1.0000x reference)
#include <cuda_runtime.h>
#include <cuda_bf16.h>
#include <cstdint>

#define N_NODES 100000
#define HID 256
#define DIN 128

// ---------------- scratch (no cudaMalloc allowed) ----------------
__device__ float g_agg[(size_t)N_NODES * HID];   // aggregation buffer (max width 256)
__device__ float g_hid[(size_t)N_NODES * HID];   // layer-1 activations
__device__ int   g_cnt_src[N_NODES];
__device__ int   g_cnt_dst[N_NODES];
__device__ float g_inv_src[N_NODES];
__device__ float g_inv_dst[N_NODES];

// ---------------- helpers ----------------
__device__ __forceinline__ void red_add4(float* p, float4 v) {
    asm volatile("red.global.add.v4.f32 [%0], {%1, %2, %3, %4};"
                 :: "l"(p), "f"(v.x), "f"(v.y), "f"(v.z), "f"(v.w)
                 : "memory");
}

__global__ void zero_f(float* __restrict__ p, size_t n4) {
    // n4 = number of float4s
    size_t i = (size_t)blockIdx.x * blockDim.x + threadIdx.x;
    size_t stride = (size_t)gridDim.x * blockDim.x;
    float4 z = make_float4(0.f, 0.f, 0.f, 0.f);
    float4* p4 = (float4*)p;
    for (; i < n4; i += stride) p4[i] = z;
}

__global__ void zero_i(int* __restrict__ p, int n) {
    int i = blockIdx.x * blockDim.x + threadIdx.x;
    if (i < n) p[i] = 0;
}

__global__ void count_deg(const int* __restrict__ src, const int* __restrict__ dst,
                          int* __restrict__ cs, int* __restrict__ cd, int E) {
    int e = blockIdx.x * blockDim.x + threadIdx.x;
    if (e < E) {
        atomicAdd(&cs[src[e]], 1);
        atomicAdd(&cd[dst[e]], 1);
    }
}

__global__ void make_inv(const int* __restrict__ c, float* __restrict__ inv, int n) {
    int i = blockIdx.x * blockDim.x + threadIdx.x;
    if (i < n) {
        int v = c[i];
        inv[i] = 1.0f / (float)(v > 0 ? v : 1);
    }
}

// One warp per edge. Gathers x[gidx[e]] (D floats), scales by inv[sidx[e]],
// scatter-adds into agg[sidx[e]]. D is 128 or 256 (multiple of 128).
__global__ __launch_bounds__(256) void aggregate(
    const float* __restrict__ x, const int* __restrict__ gidx,
    const int* __restrict__ sidx, const float* __restrict__ inv,
    float* __restrict__ agg, int E, int D)
{
    int warp = blockIdx.x * 8 + (threadIdx.x >> 5);
    int lane = threadIdx.x & 31;
    if (warp >= E) return;
    int g = __ldg(&gidx[warp]);
    int s = __ldg(&sidx[warp]);
    float w = __ldg(&inv[s]);
    const float4* srcp = (const float4*)(x + (size_t)g * D);
    float4* dstp = (float4*)(agg + (size_t)s * D);
    int n4 = D >> 2;
    for (int j = lane; j < n4; j += 32) {
        float4 v = __ldg(&srcp[j]);
        v.x *= w; v.y *= w; v.z *= w; v.w *= w;
        red_add4((float*)(dstp + j), v);
    }
}

// Fused dual GEMM + bias + ReLU:
//   out[i, :] = relu( agg[i, :K] @ Wl + x[i, :K] @ Wr + b )
// Classic 128x128x8 fp32 SGEMM, 256 threads, 8x8 per thread.
// The K-loop runs over 2K: first K from (agg, Wl), next K from (x, Wr).
__global__ __launch_bounds__(256) void sage_gemm(
    const float* __restrict__ Aagg, const float* __restrict__ Ax,
    const float* __restrict__ Wl, const float* __restrict__ Wr,
    const float* __restrict__ bias, float* __restrict__ out,
    int M, int K)
{
    __shared__ float As[8][128];
    __shared__ float Bs[8][128];

    const int tid = threadIdx.x;
    const int bm = blockIdx.x * 128;
    const int bn = blockIdx.y * 128;
    const int tx = tid & 15;       // 16 cols of threads
    const int ty = tid >> 4;       // 16 rows of threads

    float acc[8][8];
#pragma unroll
    for (int i = 0; i < 8; ++i)
#pragma unroll
        for (int j = 0; j < 8; ++j) acc[i][j] = 0.f;

    const int arow = tid >> 1;            // 0..127
    const int acol = (tid & 1) << 2;      // 0 or 4
    const int brow = tid >> 5;            // 0..7
    const int bcol = (tid & 31) << 2;     // 0..124
    const bool avalid = (bm + arow) < M;

    const int K2 = 2 * K;
    for (int kt = 0; kt < K2; kt += 8) {
        const float* A;
        const float* B;
        int k0;
        if (kt < K) { A = Aagg; B = Wl; k0 = kt; }
        else        { A = Ax;   B = Wr; k0 = kt - K; }

        float4 av = make_float4(0.f, 0.f, 0.f, 0.f);
        if (avalid)
            av = *(const float4*)(A + (size_t)(bm + arow) * K + k0 + acol);
        float4 bv = *(const float4*)(B + (size_t)(k0 + brow) * HID + bn + bcol);

        As[acol + 0][arow] = av.x;
        As[acol + 1][arow] = av.y;
        As[acol + 2][arow] = av.z;
        As[acol + 3][arow] = av.w;
        *(float4*)(&Bs[brow][bcol]) = bv;
        __syncthreads();

#pragma unroll
        for (int k = 0; k < 8; ++k) {
            float a[8], b[8];
            *(float4*)(a)     = *(const float4*)(&As[k][ty * 8]);
            *(float4*)(a + 4) = *(const float4*)(&As[k][ty * 8 + 4]);
            *(float4*)(b)     = *(const float4*)(&Bs[k][tx * 8]);
            *(float4*)(b + 4) = *(const float4*)(&Bs[k][tx * 8 + 4]);
#pragma unroll
            for (int i = 0; i < 8; ++i)
#pragma unroll
                for (int j = 0; j < 8; ++j)
                    acc[i][j] += a[i] * b[j];
        }
        __syncthreads();
    }

    // epilogue: bias + relu + store
#pragma unroll
    for (int i = 0; i < 8; ++i) {
        int row = bm + ty * 8 + i;
        if (row >= M) continue;
#pragma unroll
        for (int j = 0; j < 8; j += 4) {
            int col = bn + tx * 8 + j;
            float4 v;
            v.x = fmaxf(acc[i][j + 0] + bias[col + 0], 0.f);
            v.y = fmaxf(acc[i][j + 1] + bias[col + 1], 0.f);
            v.z = fmaxf(acc[i][j + 2] + bias[col + 2], 0.f);
            v.w = fmaxf(acc[i][j + 3] + bias[col + 3], 0.f);
            *(float4*)(out + (size_t)row * HID + col) = v;
        }
    }
}

extern "C" void kernel_launch(void* const* d_in, const int* in_sizes, int n_in,
                              void* d_out, int out_size)
{
    const float* x_human = (const float*)d_in[0];
    const float* x_bact  = (const float*)d_in[1];
    const int*   ei      = (const int*)d_in[2];
    const float* h1_Wl = (const float*)d_in[3];
    const float* h1_Wr = (const float*)d_in[4];
    const float* h1_b  = (const float*)d_in[5];
    const float* h2_Wl = (const float*)d_in[6];
    const float* h2_Wr = (const float*)d_in[7];
    const float* h2_b  = (const float*)d_in[8];
    const float* b1_Wl = (const float*)d_in[9];
    const float* b1_Wr = (const float*)d_in[10];
    const float* b1_b  = (const float*)d_in[11];
    const float* b2_Wl = (const float*)d_in[12];
    const float* b2_Wr = (const float*)d_in[13];
    const float* b2_b  = (const float*)d_in[14];

    const int N = in_sizes[0] / DIN;      // 100000
    const int E = in_sizes[2] / 2;        // 1600000
    const int* src = ei;                  // edge_index[0]
    const int* dst = ei + E;              // edge_index[1]

    float* out  = (float*)d_out;
    float* hout = out;
    float* bout = out + (size_t)N * HID;

    float *agg, *hid, *inv_s, *inv_d;
    int *cs, *cd;
    cudaGetSymbolAddress((void**)&agg,   g_agg);
    cudaGetSymbolAddress((void**)&hid,   g_hid);
    cudaGetSymbolAddress((void**)&cs,    g_cnt_src);
    cudaGetSymbolAddress((void**)&cd,    g_cnt_dst);
    cudaGetSymbolAddress((void**)&inv_s, g_inv_src);
    cudaGetSymbolAddress((void**)&inv_d, g_inv_dst);

    const int TB = 256;
    const int nb_N = (N + TB - 1) / TB;
    const int nb_E = (E + TB - 1) / TB;
    const int nb_agg = (E + 7) / 8;                 // 8 edges (warps) per block
    dim3 gemm_grid((N + 127) / 128, 2);

    // degrees -> inverse means
    zero_i<<<nb_N, TB>>>(cs, N);
    zero_i<<<nb_N, TB>>>(cd, N);
    count_deg<<<nb_E, TB>>>(src, dst, cs, cd, E);
    make_inv<<<nb_N, TB>>>(cs, inv_s, N);
    make_inv<<<nb_N, TB>>>(cd, inv_d, N);

    // ---- human branch: gather by dst, scatter to src (rev edges) ----
    zero_f<<<2048, TB>>>(agg, ((size_t)N * DIN) >> 2);
    aggregate<<<nb_agg, TB>>>(x_human, dst, src, inv_s, agg, E, DIN);
    sage_gemm<<<gemm_grid, TB>>>(agg, x_human, h1_Wl, h1_Wr, h1_b, hid, N, DIN);

    zero_f<<<2048, TB>>>(agg, ((size_t)N * HID) >> 2);
    aggregate<<<nb_agg, TB>>>(hid, dst, src, inv_s, agg, E, HID);
    sage_gemm<<<gemm_grid, TB>>>(agg, hid, h2_Wl, h2_Wr, h2_b, hout, N, HID);

    // ---- bacterial branch: gather by src, scatter to dst ----
    zero_f<<<2048, TB>>>(agg, ((size_t)N * DIN) >> 2);
    aggregate<<<nb_agg, TB>>>(x_bact, src, dst, inv_d, agg, E, DIN);
    sage_gemm<<<gemm_grid, TB>>>(agg, x_bact, b1_Wl, b1_Wr, b1_b, hid, N, DIN);

    zero_f<<<2048, TB>>>(agg, ((size_t)N * HID) >> 2);
    aggregate<<<nb_agg, TB>>>(hid, src, dst, inv_d, agg, E, HID);
    sage_gemm<<<gemm_grid, TB>>>(agg, hid, b2_Wl, b2_Wr, b2_b, bout, N, HID);
}

// round 3
// speedup vs baseline: 1.2655x; 1.2655x over previous
#include <cuda_runtime.h>
#include <cuda_bf16.h>
#include <cstdint>

#define N_NODES 100000
#define HID 256
#define DIN 128

// ---------------- scratch (no cudaMalloc allowed) ----------------
__device__ float g_agg[(size_t)N_NODES * HID];   // aggregation buffer (max width 256)
__device__ float g_hid[(size_t)N_NODES * HID];   // layer-1 activations
__device__ int   g_cnt_src[N_NODES];
__device__ int   g_cnt_dst[N_NODES];
__device__ float g_inv_src[N_NODES];
__device__ float g_inv_dst[N_NODES];

// ---------------- helpers ----------------
__device__ __forceinline__ void red_add4(float* p, float4 v) {
    asm volatile("red.global.add.v4.f32 [%0], {%1, %2, %3, %4};"
                 :: "l"(p), "f"(v.x), "f"(v.y), "f"(v.z), "f"(v.w)
                 : "memory");
}

__device__ __forceinline__ unsigned f2tf32(float f) {
    unsigned u;
    asm("cvt.rna.tf32.f32 %0, %1;" : "=r"(u) : "f"(f));
    return u;
}

__device__ __forceinline__ void mma1688(float* c, const unsigned* a, const unsigned* b) {
    asm volatile(
        "mma.sync.aligned.m16n8k8.row.col.f32.tf32.tf32.f32 "
        "{%0,%1,%2,%3}, {%4,%5,%6,%7}, {%8,%9}, {%0,%1,%2,%3};"
        : "+f"(c[0]), "+f"(c[1]), "+f"(c[2]), "+f"(c[3])
        : "r"(a[0]), "r"(a[1]), "r"(a[2]), "r"(a[3]),
          "r"(b[0]), "r"(b[1]));
}

__global__ void zero_f(float* __restrict__ p, size_t n4) {
    size_t i = (size_t)blockIdx.x * blockDim.x + threadIdx.x;
    size_t stride = (size_t)gridDim.x * blockDim.x;
    float4 z = make_float4(0.f, 0.f, 0.f, 0.f);
    float4* p4 = (float4*)p;
    for (; i < n4; i += stride) p4[i] = z;
}

__global__ void zero_i(int* __restrict__ p, int n) {
    int i = blockIdx.x * blockDim.x + threadIdx.x;
    if (i < n) p[i] = 0;
}

__global__ void count_deg(const int* __restrict__ src, const int* __restrict__ dst,
                          int* __restrict__ cs, int* __restrict__ cd, int E) {
    int e = blockIdx.x * blockDim.x + threadIdx.x;
    if (e < E) {
        atomicAdd(&cs[src[e]], 1);
        atomicAdd(&cd[dst[e]], 1);
    }
}

__global__ void make_inv(const int* __restrict__ c, float* __restrict__ inv, int n) {
    int i = blockIdx.x * blockDim.x + threadIdx.x;
    if (i < n) {
        int v = c[i];
        inv[i] = 1.0f / (float)(v > 0 ? v : 1);
    }
}

// One warp per edge. Gathers x[gidx[e]] (D floats), scales by inv[sidx[e]],
// scatter-adds into agg[sidx[e]].
__global__ __launch_bounds__(256) void aggregate(
    const float* __restrict__ x, const int* __restrict__ gidx,
    const int* __restrict__ sidx, const float* __restrict__ inv,
    float* __restrict__ agg, int E, int D)
{
    int warp = blockIdx.x * 8 + (threadIdx.x >> 5);
    int lane = threadIdx.x & 31;
    if (warp >= E) return;
    int g = __ldg(&gidx[warp]);
    int s = __ldg(&sidx[warp]);
    float w = __ldg(&inv[s]);
    const float4* srcp = (const float4*)(x + (size_t)g * D);
    float4* dstp = (float4*)(agg + (size_t)s * D);
    int n4 = D >> 2;
    for (int j = lane; j < n4; j += 32) {
        float4 v = __ldg(&srcp[j]);
        v.x *= w; v.y *= w; v.z *= w; v.w *= w;
        red_add4((float*)(dstp + j), v);
    }
}

// ---------------------------------------------------------------------------
// TF32 tensor-core fused dual GEMM + bias + ReLU:
//   out[i,:] = relu( agg[i,:K] @ Wl + x[i,:K] @ Wr + b )
// 128x128 CTA tile, BK=8, double-buffered smem, 8 warps each 64x32.
// K-loop runs over 2K: first K from (agg, Wl), then K from (x, Wr).
// ---------------------------------------------------------------------------
#define BM 128
#define BN 128
#define BK 8
#define AS_STR 132   // m-stride with pad
#define BS_STR 12    // k-stride with pad

__global__ __launch_bounds__(256) void sage_gemm_tf32(
    const float* __restrict__ Aagg, const float* __restrict__ Ax,
    const float* __restrict__ Wl, const float* __restrict__ Wr,
    const float* __restrict__ bias, float* __restrict__ out,
    int M, int K)
{
    __shared__ unsigned As[2][BK][AS_STR];     // As[s][k][m]
    __shared__ unsigned Bs[2][BN][BS_STR];     // Bs[s][n][k]

    const int tid  = threadIdx.x;
    const int lane = tid & 31;
    const int warp = tid >> 5;
    const int wm = (warp & 1) * 64;   // warp row offset
    const int wn = (warp >> 1) * 32;  // warp col offset
    const int bm = blockIdx.x * BM;
    const int bn = blockIdx.y * BN;

    float acc[4][4][4];
#pragma unroll
    for (int mi = 0; mi < 4; ++mi)
#pragma unroll
        for (int ni = 0; ni < 4; ++ni)
#pragma unroll
            for (int c = 0; c < 4; ++c) acc[mi][ni][c] = 0.f;

    // global load mapping
    const int arow  = tid >> 1;            // 0..127
    const int akoff = (tid & 1) << 2;      // 0 or 4
    const int bkrow = tid >> 5;            // 0..7
    const int bn4   = (tid & 31) << 2;     // 0..124
    const bool avalid = (bm + arow) < M;

    const int K2 = 2 * K;

    float4 av, bv;
    {
        // prologue load kt=0 (always from Aagg/Wl)
        av = make_float4(0.f, 0.f, 0.f, 0.f);
        if (avalid) av = *(const float4*)(Aagg + (size_t)(bm + arow) * K + akoff);
        bv = *(const float4*)(Wl + (size_t)bkrow * HID + bn + bn4);
        As[0][akoff + 0][arow] = f2tf32(av.x);
        As[0][akoff + 1][arow] = f2tf32(av.y);
        As[0][akoff + 2][arow] = f2tf32(av.z);
        As[0][akoff + 3][arow] = f2tf32(av.w);
        Bs[0][bn4 + 0][bkrow] = f2tf32(bv.x);
        Bs[0][bn4 + 1][bkrow] = f2tf32(bv.y);
        Bs[0][bn4 + 2][bkrow] = f2tf32(bv.z);
        Bs[0][bn4 + 3][bkrow] = f2tf32(bv.w);
    }
    __syncthreads();

    int s = 0;
    for (int kt = 0; kt < K2; kt += BK) {
        const int nkt = kt + BK;
        const bool has_next = nkt < K2;
        float4 av2, bv2;
        if (has_next) {
            const float* A; const float* B; int k0;
            if (nkt < K) { A = Aagg; B = Wl; k0 = nkt; }
            else         { A = Ax;   B = Wr; k0 = nkt - K; }
            av2 = make_float4(0.f, 0.f, 0.f, 0.f);
            if (avalid) av2 = *(const float4*)(A + (size_t)(bm + arow) * K + k0 + akoff);
            bv2 = *(const float4*)(B + (size_t)(k0 + bkrow) * HID + bn + bn4);
        }

        // fragments from stage s
        unsigned a[4][4], b[4][2];
        const int qk = lane & 3;
        const int qr = lane >> 2;
#pragma unroll
        for (int mi = 0; mi < 4; ++mi) {
            int m0 = wm + mi * 16 + qr;
            a[mi][0] = As[s][qk][m0];
            a[mi][1] = As[s][qk][m0 + 8];
            a[mi][2] = As[s][qk + 4][m0];
            a[mi][3] = As[s][qk + 4][m0 + 8];
        }
#pragma unroll
        for (int ni = 0; ni < 4; ++ni) {
            int n0 = wn + ni * 8 + qr;
            b[ni][0] = Bs[s][n0][qk];
            b[ni][1] = Bs[s][n0][qk + 4];
        }
#pragma unroll
        for (int mi = 0; mi < 4; ++mi)
#pragma unroll
            for (int ni = 0; ni < 4; ++ni)
                mma1688(acc[mi][ni], a[mi], b[ni]);

        if (has_next) {
            int t = s ^ 1;
            As[t][akoff + 0][arow] = f2tf32(av2.x);
            As[t][akoff + 1][arow] = f2tf32(av2.y);
            As[t][akoff + 2][arow] = f2tf32(av2.z);
            As[t][akoff + 3][arow] = f2tf32(av2.w);
            Bs[t][bn4 + 0][bkrow] = f2tf32(bv2.x);
            Bs[t][bn4 + 1][bkrow] = f2tf32(bv2.y);
            Bs[t][bn4 + 2][bkrow] = f2tf32(bv2.z);
            Bs[t][bn4 + 3][bkrow] = f2tf32(bv2.w);
        }
        __syncthreads();
        s ^= 1;
    }

    // epilogue: bias + relu + store (float2 per c-pair)
    const int qk = lane & 3;
    const int qr = lane >> 2;
#pragma unroll
    for (int mi = 0; mi < 4; ++mi) {
        int r0 = bm + wm + mi * 16 + qr;
#pragma unroll
        for (int ni = 0; ni < 4; ++ni) {
            int c0 = bn + wn + ni * 8 + qk * 2;
            float bb0 = bias[c0];
            float bb1 = bias[c0 + 1];
            if (r0 < M) {
                float2 v;
                v.x = fmaxf(acc[mi][ni][0] + bb0, 0.f);
                v.y = fmaxf(acc[mi][ni][1] + bb1, 0.f);
                *(float2*)(out + (size_t)r0 * HID + c0) = v;
            }
            if (r0 + 8 < M) {
                float2 v;
                v.x = fmaxf(acc[mi][ni][2] + bb0, 0.f);
                v.y = fmaxf(acc[mi][ni][3] + bb1, 0.f);
                *(float2*)(out + (size_t)(r0 + 8) * HID + c0) = v;
            }
        }
    }
}

extern "C" void kernel_launch(void* const* d_in, const int* in_sizes, int n_in,
                              void* d_out, int out_size)
{
    const float* x_human = (const float*)d_in[0];
    const float* x_bact  = (const float*)d_in[1];
    const int*   ei      = (const int*)d_in[2];
    const float* h1_Wl = (const float*)d_in[3];
    const float* h1_Wr = (const float*)d_in[4];
    const float* h1_b  = (const float*)d_in[5];
    const float* h2_Wl = (const float*)d_in[6];
    const float* h2_Wr = (const float*)d_in[7];
    const float* h2_b  = (const float*)d_in[8];
    const float* b1_Wl = (const float*)d_in[9];
    const float* b1_Wr = (const float*)d_in[10];
    const float* b1_b  = (const float*)d_in[11];
    const float* b2_Wl = (const float*)d_in[12];
    const float* b2_Wr = (const float*)d_in[13];
    const float* b2_b  = (const float*)d_in[14];

    const int N = in_sizes[0] / DIN;      // 100000
    const int E = in_sizes[2] / 2;        // 1600000
    const int* src = ei;                  // edge_index[0]
    const int* dst = ei + E;              // edge_index[1]

    float* out  = (float*)d_out;
    float* hout = out;
    float* bout = out + (size_t)N * HID;

    float *agg, *hid, *inv_s, *inv_d;
    int *cs, *cd;
    cudaGetSymbolAddress((void**)&agg,   g_agg);
    cudaGetSymbolAddress((void**)&hid,   g_hid);
    cudaGetSymbolAddress((void**)&cs,    g_cnt_src);
    cudaGetSymbolAddress((void**)&cd,    g_cnt_dst);
    cudaGetSymbolAddress((void**)&inv_s, g_inv_src);
    cudaGetSymbolAddress((void**)&inv_d, g_inv_dst);

    const int TB = 256;
    const int nb_N = (N + TB - 1) / TB;
    const int nb_E = (E + TB - 1) / TB;
    const int nb_agg = (E + 7) / 8;                 // 8 edges (warps) per block
    dim3 gemm_grid((N + 127) / 128, 2);

    // degrees -> inverse means
    zero_i<<<nb_N, TB>>>(cs, N);
    zero_i<<<nb_N, TB>>>(cd, N);
    count_deg<<<nb_E, TB>>>(src, dst, cs, cd, E);
    make_inv<<<nb_N, TB>>>(cs, inv_s, N);
    make_inv<<<nb_N, TB>>>(cd, inv_d, N);

    // ---- human branch: gather by dst, scatter to src (rev edges) ----
    zero_f<<<2048, TB>>>(agg, ((size_t)N * DIN) >> 2);
    aggregate<<<nb_agg, TB>>>(x_human, dst, src, inv_s, agg, E, DIN);
    sage_gemm_tf32<<<gemm_grid, TB>>>(agg, x_human, h1_Wl, h1_Wr, h1_b, hid, N, DIN);

    zero_f<<<2048, TB>>>(agg, ((size_t)N * HID) >> 2);
    aggregate<<<nb_agg, TB>>>(hid, dst, src, inv_s, agg, E, HID);
    sage_gemm_tf32<<<gemm_grid, TB>>>(agg, hid, h2_Wl, h2_Wr, h2_b, hout, N, HID);

    // ---- bacterial branch: gather by src, scatter to dst ----
    zero_f<<<2048, TB>>>(agg, ((size_t)N * DIN) >> 2);
    aggregate<<<nb_agg, TB>>>(x_bact, src, dst, inv_d, agg, E, DIN);
    sage_gemm_tf32<<<gemm_grid, TB>>>(agg, x_bact, b1_Wl, b1_Wr, b1_b, hid, N, DIN);

    zero_f<<<2048, TB>>>(agg, ((size_t)N * HID) >> 2);
    aggregate<<<nb_agg, TB>>>(hid, src, dst, inv_d, agg, E, HID);
    sage_gemm_tf32<<<gemm_grid, TB>>>(agg, hid, b2_Wl, b2_Wr, b2_b, bout, N, HID);
}

// round 4
// speedup vs baseline: 1.8692x; 1.4771x over previous
#include <cuda_runtime.h>
#include <cuda_bf16.h>
#include <cstdint>

#define N_NODES 100000
#define HID 256
#define DIN 128
#define E_MAX 1600000
#define SCAN_B 256
#define NB_MAX 512   // max scan blocks per direction (ceil(100000/256)=391)

// ---------------- scratch (no cudaMalloc allowed) ----------------
__device__ float g_agg[(size_t)N_NODES * HID];   // aggregation buffer
__device__ float g_hid[(size_t)N_NODES * HID];   // layer-1 activations
__device__ int   g_cnt[2 * N_NODES];             // [0]=by-src counts, [1]=by-dst
__device__ int   g_part[2 * NB_MAX];             // scan partials
__device__ int   g_rowptr[2 * (N_NODES + 1)];
__device__ int   g_cursor[2 * N_NODES];
__device__ int   g_adj[2 * E_MAX];               // adjacency (gather indices)

// ---------------- tf32 helpers ----------------
__device__ __forceinline__ unsigned f2tf32(float f) {
    unsigned u;
    asm("cvt.rna.tf32.f32 %0, %1;" : "=r"(u) : "f"(f));
    return u;
}

__device__ __forceinline__ void mma1688(float* c, const unsigned* a, const unsigned* b) {
    asm volatile(
        "mma.sync.aligned.m16n8k8.row.col.f32.tf32.tf32.f32 "
        "{%0,%1,%2,%3}, {%4,%5,%6,%7}, {%8,%9}, {%0,%1,%2,%3};"
        : "+f"(c[0]), "+f"(c[1]), "+f"(c[2]), "+f"(c[3])
        : "r"(a[0]), "r"(a[1]), "r"(a[2]), "r"(a[3]),
          "r"(b[0]), "r"(b[1]));
}

// ---------------- CSR build ----------------
__global__ void count_deg(const int* __restrict__ src, const int* __restrict__ dst,
                          int* __restrict__ cnt, int E) {
    int e = blockIdx.x * blockDim.x + threadIdx.x;
    if (e < E) {
        atomicAdd(&cnt[src[e]], 1);               // by-src
        atomicAdd(&cnt[N_NODES + dst[e]], 1);     // by-dst
    }
}

// inclusive scan of v over 256-thread block (8 warps)
__device__ __forceinline__ int block_incl_scan256(int v, int* warpS) {
    int lane = threadIdx.x & 31, w = threadIdx.x >> 5;
#pragma unroll
    for (int o = 1; o < 32; o <<= 1) {
        int t = __shfl_up_sync(0xffffffffu, v, o);
        if (lane >= o) v += t;
    }
    if (lane == 31) warpS[w] = v;
    __syncthreads();
    if (w == 0) {
        int s = (lane < 8) ? warpS[lane] : 0;
#pragma unroll
        for (int o = 1; o < 8; o <<= 1) {
            int t = __shfl_up_sync(0xffffffffu, s, o);
            if (lane >= o) s += t;
        }
        if (lane < 8) warpS[lane] = s;
    }
    __syncthreads();
    int add = (w > 0) ? warpS[w - 1] : 0;
    return v + add;
}

// phase 1: per-block totals
__global__ void scan_reduce(const int* __restrict__ cnt, int* __restrict__ part, int n) {
    __shared__ int warpS[8];
    int dir = blockIdx.y;
    int i = blockIdx.x * SCAN_B + threadIdx.x;
    int v = (i < n) ? cnt[dir * N_NODES + i] : 0;
    int incl = block_incl_scan256(v, warpS);
    if (threadIdx.x == SCAN_B - 1) part[dir * NB_MAX + blockIdx.x] = incl;
}

// phase 2: exclusive scan of partials (one block per direction, 512 threads, 16 warps)
__global__ void scan_top(int* __restrict__ part, int nb) {
    __shared__ int warpS[16];
    int dir = blockIdx.y;
    int lane = threadIdx.x & 31, w = threadIdx.x >> 5;
    int v = (threadIdx.x < nb) ? part[dir * NB_MAX + threadIdx.x] : 0;
    int incl = v;
#pragma unroll
    for (int o = 1; o < 32; o <<= 1) {
        int t = __shfl_up_sync(0xffffffffu, incl, o);
        if (lane >= o) incl += t;
    }
    if (lane == 31) warpS[w] = incl;
    __syncthreads();
    if (w == 0) {
        int s = (lane < 16) ? warpS[lane] : 0;
#pragma unroll
        for (int o = 1; o < 16; o <<= 1) {
            int t = __shfl_up_sync(0xffffffffu, s, o);
            if (lane >= o) s += t;
        }
        if (lane < 16) warpS[lane] = s;
    }
    __syncthreads();
    if (w > 0) incl += warpS[w - 1];
    if (threadIdx.x < nb) part[dir * NB_MAX + threadIdx.x] = incl - v;  // exclusive
}

// phase 3: write rowptr + cursor
__global__ void scan_write(const int* __restrict__ cnt, const int* __restrict__ part,
                           int* __restrict__ rowptr, int* __restrict__ cursor, int n, int E) {
    __shared__ int warpS[8];
    int dir = blockIdx.y;
    int i = blockIdx.x * SCAN_B + threadIdx.x;
    int v = (i < n) ? cnt[dir * N_NODES + i] : 0;
    int incl = block_incl_scan256(v, warpS);
    int ex = incl - v + part[dir * NB_MAX + blockIdx.x];
    if (i < n) {
        rowptr[dir * (N_NODES + 1) + i] = ex;
        cursor[dir * N_NODES + i] = ex;
        if (i == n - 1) rowptr[dir * (N_NODES + 1) + n] = E;
    }
}

__global__ void scatter_adj(const int* __restrict__ src, const int* __restrict__ dst,
                            int* __restrict__ cursor, int* __restrict__ adj, int E) {
    int e = blockIdx.x * blockDim.x + threadIdx.x;
    if (e < E) {
        int s = src[e], d = dst[e];
        int p0 = atomicAdd(&cursor[s], 1);
        adj[p0] = d;                               // by-src list gathers dst
        int p1 = atomicAdd(&cursor[N_NODES + d], 1);
        adj[E_MAX + p1] = s;                       // by-dst list gathers src
    }
}

// ---------------- CSR aggregation: one warp per node, no atomics ----------------
__global__ __launch_bounds__(256) void aggregate_csr(
    const float* __restrict__ x, const int* __restrict__ rowptr,
    const int* __restrict__ adj, float* __restrict__ agg, int Nn, int D)
{
    int node = blockIdx.x * 8 + (threadIdx.x >> 5);
    if (node >= Nn) return;
    int lane = threadIdx.x & 31;
    int p0 = __ldg(&rowptr[node]);
    int p1 = __ldg(&rowptr[node + 1]);
    int deg = p1 - p0;
    float inv = 1.0f / (float)(deg > 0 ? deg : 1);
    const bool wide = (D > 128);

    float4 a0 = make_float4(0.f, 0.f, 0.f, 0.f);
    float4 a1 = make_float4(0.f, 0.f, 0.f, 0.f);

    int p = p0;
    for (; p + 1 < p1; p += 2) {
        int g0 = __ldg(&adj[p]);
        int g1 = __ldg(&adj[p + 1]);
        const float4* r0 = (const float4*)(x + (size_t)g0 * D);
        const float4* r1 = (const float4*)(x + (size_t)g1 * D);
        float4 v0 = __ldg(&r0[lane]);
        float4 v1 = __ldg(&r1[lane]);
        a0.x += v0.x + v1.x; a0.y += v0.y + v1.y;
        a0.z += v0.z + v1.z; a0.w += v0.w + v1.w;
        if (wide) {
            float4 w0 = __ldg(&r0[lane + 32]);
            float4 w1 = __ldg(&r1[lane + 32]);
            a1.x += w0.x + w1.x; a1.y += w0.y + w1.y;
            a1.z += w0.z + w1.z; a1.w += w0.w + w1.w;
        }
    }
    if (p < p1) {
        int g0 = __ldg(&adj[p]);
        const float4* r0 = (const float4*)(x + (size_t)g0 * D);
        float4 v0 = __ldg(&r0[lane]);
        a0.x += v0.x; a0.y += v0.y; a0.z += v0.z; a0.w += v0.w;
        if (wide) {
            float4 w0 = __ldg(&r0[lane + 32]);
            a1.x += w0.x; a1.y += w0.y; a1.z += w0.z; a1.w += w0.w;
        }
    }

    float4* op = (float4*)(agg + (size_t)node * D);
    a0.x *= inv; a0.y *= inv; a0.z *= inv; a0.w *= inv;
    op[lane] = a0;
    if (wide) {
        a1.x *= inv; a1.y *= inv; a1.z *= inv; a1.w *= inv;
        op[lane + 32] = a1;
    }
}

// ---------------------------------------------------------------------------
// TF32 tensor-core fused dual GEMM + bias + ReLU (unchanged from R3)
// ---------------------------------------------------------------------------
#define BM 128
#define BN 128
#define BK 8
#define AS_STR 132
#define BS_STR 12

__global__ __launch_bounds__(256) void sage_gemm_tf32(
    const float* __restrict__ Aagg, const float* __restrict__ Ax,
    const float* __restrict__ Wl, const float* __restrict__ Wr,
    const float* __restrict__ bias, float* __restrict__ out,
    int M, int K)
{
    __shared__ unsigned As[2][BK][AS_STR];
    __shared__ unsigned Bs[2][BN][BS_STR];

    const int tid  = threadIdx.x;
    const int lane = tid & 31;
    const int warp = tid >> 5;
    const int wm = (warp & 1) * 64;
    const int wn = (warp >> 1) * 32;
    const int bm = blockIdx.x * BM;
    const int bn = blockIdx.y * BN;

    float acc[4][4][4];
#pragma unroll
    for (int mi = 0; mi < 4; ++mi)
#pragma unroll
        for (int ni = 0; ni < 4; ++ni)
#pragma unroll
            for (int c = 0; c < 4; ++c) acc[mi][ni][c] = 0.f;

    const int arow  = tid >> 1;
    const int akoff = (tid & 1) << 2;
    const int bkrow = tid >> 5;
    const int bn4   = (tid & 31) << 2;
    const bool avalid = (bm + arow) < M;

    const int K2 = 2 * K;

    {
        float4 av = make_float4(0.f, 0.f, 0.f, 0.f);
        if (avalid) av = *(const float4*)(Aagg + (size_t)(bm + arow) * K + akoff);
        float4 bv = *(const float4*)(Wl + (size_t)bkrow * HID + bn + bn4);
        As[0][akoff + 0][arow] = f2tf32(av.x);
        As[0][akoff + 1][arow] = f2tf32(av.y);
        As[0][akoff + 2][arow] = f2tf32(av.z);
        As[0][akoff + 3][arow] = f2tf32(av.w);
        Bs[0][bn4 + 0][bkrow] = f2tf32(bv.x);
        Bs[0][bn4 + 1][bkrow] = f2tf32(bv.y);
        Bs[0][bn4 + 2][bkrow] = f2tf32(bv.z);
        Bs[0][bn4 + 3][bkrow] = f2tf32(bv.w);
    }
    __syncthreads();

    int s = 0;
    for (int kt = 0; kt < K2; kt += BK) {
        const int nkt = kt + BK;
        const bool has_next = nkt < K2;
        float4 av2, bv2;
        if (has_next) {
            const float* A; const float* B; int k0;
            if (nkt < K) { A = Aagg; B = Wl; k0 = nkt; }
            else         { A = Ax;   B = Wr; k0 = nkt - K; }
            av2 = make_float4(0.f, 0.f, 0.f, 0.f);
            if (avalid) av2 = *(const float4*)(A + (size_t)(bm + arow) * K + k0 + akoff);
            bv2 = *(const float4*)(B + (size_t)(k0 + bkrow) * HID + bn + bn4);
        }

        unsigned a[4][4], b[4][2];
        const int qk = lane & 3;
        const int qr = lane >> 2;
#pragma unroll
        for (int mi = 0; mi < 4; ++mi) {
            int m0 = wm + mi * 16 + qr;
            a[mi][0] = As[s][qk][m0];
            a[mi][1] = As[s][qk][m0 + 8];
            a[mi][2] = As[s][qk + 4][m0];
            a[mi][3] = As[s][qk + 4][m0 + 8];
        }
#pragma unroll
        for (int ni = 0; ni < 4; ++ni) {
            int n0 = wn + ni * 8 + qr;
            b[ni][0] = Bs[s][n0][qk];
            b[ni][1] = Bs[s][n0][qk + 4];
        }
#pragma unroll
        for (int mi = 0; mi < 4; ++mi)
#pragma unroll
            for (int ni = 0; ni < 4; ++ni)
                mma1688(acc[mi][ni], a[mi], b[ni]);

        if (has_next) {
            int t = s ^ 1;
            As[t][akoff + 0][arow] = f2tf32(av2.x);
            As[t][akoff + 1][arow] = f2tf32(av2.y);
            As[t][akoff + 2][arow] = f2tf32(av2.z);
            As[t][akoff + 3][arow] = f2tf32(av2.w);
            Bs[t][bn4 + 0][bkrow] = f2tf32(bv2.x);
            Bs[t][bn4 + 1][bkrow] = f2tf32(bv2.y);
            Bs[t][bn4 + 2][bkrow] = f2tf32(bv2.z);
            Bs[t][bn4 + 3][bkrow] = f2tf32(bv2.w);
        }
        __syncthreads();
        s ^= 1;
    }

    const int qk = lane & 3;
    const int qr = lane >> 2;
#pragma unroll
    for (int mi = 0; mi < 4; ++mi) {
        int r0 = bm + wm + mi * 16 + qr;
#pragma unroll
        for (int ni = 0; ni < 4; ++ni) {
            int c0 = bn + wn + ni * 8 + qk * 2;
            float bb0 = bias[c0];
            float bb1 = bias[c0 + 1];
            if (r0 < M) {
                float2 v;
                v.x = fmaxf(acc[mi][ni][0] + bb0, 0.f);
                v.y = fmaxf(acc[mi][ni][1] + bb1, 0.f);
                *(float2*)(out + (size_t)r0 * HID + c0) = v;
            }
            if (r0 + 8 < M) {
                float2 v;
                v.x = fmaxf(acc[mi][ni][2] + bb0, 0.f);
                v.y = fmaxf(acc[mi][ni][3] + bb1, 0.f);
                *(float2*)(out + (size_t)(r0 + 8) * HID + c0) = v;
            }
        }
    }
}

extern "C" void kernel_launch(void* const* d_in, const int* in_sizes, int n_in,
                              void* d_out, int out_size)
{
    const float* x_human = (const float*)d_in[0];
    const float* x_bact  = (const float*)d_in[1];
    const int*   ei      = (const int*)d_in[2];
    const float* h1_Wl = (const float*)d_in[3];
    const float* h1_Wr = (const float*)d_in[4];
    const float* h1_b  = (const float*)d_in[5];
    const float* h2_Wl = (const float*)d_in[6];
    const float* h2_Wr = (const float*)d_in[7];
    const float* h2_b  = (const float*)d_in[8];
    const float* b1_Wl = (const float*)d_in[9];
    const float* b1_Wr = (const float*)d_in[10];
    const float* b1_b  = (const float*)d_in[11];
    const float* b2_Wl = (const float*)d_in[12];
    const float* b2_Wr = (const float*)d_in[13];
    const float* b2_b  = (const float*)d_in[14];

    const int N = in_sizes[0] / DIN;      // 100000
    const int E = in_sizes[2] / 2;        // 1600000
    const int* src = ei;
    const int* dst = ei + E;

    float* out  = (float*)d_out;
    float* hout = out;
    float* bout = out + (size_t)N * HID;

    float *agg, *hid;
    int *cnt, *part, *rowptr, *cursor, *adj;
    cudaGetSymbolAddress((void**)&agg,    g_agg);
    cudaGetSymbolAddress((void**)&hid,    g_hid);
    cudaGetSymbolAddress((void**)&cnt,    g_cnt);
    cudaGetSymbolAddress((void**)&part,   g_part);
    cudaGetSymbolAddress((void**)&rowptr, g_rowptr);
    cudaGetSymbolAddress((void**)&cursor, g_cursor);
    cudaGetSymbolAddress((void**)&adj,    g_adj);

    const int* rp_s = rowptr;                 // by-src rowptr
    const int* rp_d = rowptr + (N_NODES + 1); // by-dst rowptr
    const int* adj_s = adj;                   // by-src adjacency (gathers dst)
    const int* adj_d = adj + E_MAX;           // by-dst adjacency (gathers src)

    const int TB = 256;
    const int nb_N = (N + TB - 1) / TB;       // 391
    const int nb_E = (E + TB - 1) / TB;
    const int nb_agg = (N * 32 + TB - 1) / TB;
    dim3 gemm_grid((N + 127) / 128, 2);
    dim3 scan_grid(nb_N, 2);
    dim3 top_grid(1, 2);

    // ---- CSR build ----
    cudaMemsetAsync(cnt, 0, 2 * N_NODES * sizeof(int));
    count_deg<<<nb_E, TB>>>(src, dst, cnt, E);
    scan_reduce<<<scan_grid, TB>>>(cnt, part, N);
    scan_top<<<top_grid, 512>>>(part, nb_N);
    scan_write<<<scan_grid, TB>>>(cnt, part, rowptr, cursor, N, E);
    scatter_adj<<<nb_E, TB>>>(src, dst, cursor, adj, E);

    // ---- human branch: aggregate over by-src CSR (gathers dst rows) ----
    aggregate_csr<<<nb_agg, TB>>>(x_human, rp_s, adj_s, agg, N, DIN);
    sage_gemm_tf32<<<gemm_grid, TB>>>(agg, x_human, h1_Wl, h1_Wr, h1_b, hid, N, DIN);
    aggregate_csr<<<nb_agg, TB>>>(hid, rp_s, adj_s, agg, N, HID);
    sage_gemm_tf32<<<gemm_grid, TB>>>(agg, hid, h2_Wl, h2_Wr, h2_b, hout, N, HID);

    // ---- bacterial branch: aggregate over by-dst CSR (gathers src rows) ----
    aggregate_csr<<<nb_agg, TB>>>(x_bact, rp_d, adj_d, agg, N, DIN);
    sage_gemm_tf32<<<gemm_grid, TB>>>(agg, x_bact, b1_Wl, b1_Wr, b1_b, hid, N, DIN);
    aggregate_csr<<<nb_agg, TB>>>(hid, rp_d, adj_d, agg, N, HID);
    sage_gemm_tf32<<<gemm_grid, TB>>>(agg, hid, b2_Wl, b2_Wr, b2_b, bout, N, HID);
}

// round 5
// speedup vs baseline: 2.0012x; 1.0706x over previous
#include <cuda_runtime.h>
#include <cuda_bf16.h>
#include <cstdint>

#define N_NODES 100000
#define HID 256
#define DIN 128
#define E_MAX 1600000
#define SCAN_B 256
#define NB_MAX 512

// ---------------- scratch (no cudaMalloc allowed) ----------------
__device__ float g_agg [(size_t)N_NODES * HID];   // human branch agg
__device__ float g_hid [(size_t)N_NODES * HID];   // human branch layer-1 act
__device__ float g_agg2[(size_t)N_NODES * HID];   // bacterial branch agg
__device__ float g_hid2[(size_t)N_NODES * HID];   // bacterial branch layer-1 act
__device__ int   g_cnt[2 * N_NODES];
__device__ int   g_part[2 * NB_MAX];
__device__ int   g_rowptr[2 * (N_NODES + 1)];
__device__ int   g_cursor[2 * N_NODES];
__device__ int   g_adj[2 * E_MAX];

// ---------------- one-time stream/event resources (no device memory) -------
static cudaStream_t g_s1;
static cudaEvent_t  g_ev_fork, g_ev_join;
static bool g_par_ok = false;
namespace {
struct _StreamInit {
    _StreamInit() {
        bool ok = true;
        ok = ok && (cudaStreamCreateWithFlags(&g_s1, cudaStreamNonBlocking) == cudaSuccess);
        ok = ok && (cudaEventCreateWithFlags(&g_ev_fork, cudaEventDisableTiming) == cudaSuccess);
        ok = ok && (cudaEventCreateWithFlags(&g_ev_join, cudaEventDisableTiming) == cudaSuccess);
        g_par_ok = ok;
    }
};
static _StreamInit _stream_init;
}

// ---------------- tf32 helpers ----------------
__device__ __forceinline__ unsigned f2tf32(float f) {
    unsigned u;
    asm("cvt.rna.tf32.f32 %0, %1;" : "=r"(u) : "f"(f));
    return u;
}

__device__ __forceinline__ void mma1688(float* c, const unsigned* a, const unsigned* b) {
    asm volatile(
        "mma.sync.aligned.m16n8k8.row.col.f32.tf32.tf32.f32 "
        "{%0,%1,%2,%3}, {%4,%5,%6,%7}, {%8,%9}, {%0,%1,%2,%3};"
        : "+f"(c[0]), "+f"(c[1]), "+f"(c[2]), "+f"(c[3])
        : "r"(a[0]), "r"(a[1]), "r"(a[2]), "r"(a[3]),
          "r"(b[0]), "r"(b[1]));
}

// ---------------- CSR build ----------------
__global__ void count_deg(const int* __restrict__ src, const int* __restrict__ dst,
                          int* __restrict__ cnt, int E) {
    int e = blockIdx.x * blockDim.x + threadIdx.x;
    if (e < E) {
        atomicAdd(&cnt[src[e]], 1);
        atomicAdd(&cnt[N_NODES + dst[e]], 1);
    }
}

__device__ __forceinline__ int block_incl_scan256(int v, int* warpS) {
    int lane = threadIdx.x & 31, w = threadIdx.x >> 5;
#pragma unroll
    for (int o = 1; o < 32; o <<= 1) {
        int t = __shfl_up_sync(0xffffffffu, v, o);
        if (lane >= o) v += t;
    }
    if (lane == 31) warpS[w] = v;
    __syncthreads();
    if (w == 0) {
        int s = (lane < 8) ? warpS[lane] : 0;
#pragma unroll
        for (int o = 1; o < 8; o <<= 1) {
            int t = __shfl_up_sync(0xffffffffu, s, o);
            if (lane >= o) s += t;
        }
        if (lane < 8) warpS[lane] = s;
    }
    __syncthreads();
    int add = (w > 0) ? warpS[w - 1] : 0;
    return v + add;
}

__global__ void scan_reduce(const int* __restrict__ cnt, int* __restrict__ part, int n) {
    __shared__ int warpS[8];
    int dir = blockIdx.y;
    int i = blockIdx.x * SCAN_B + threadIdx.x;
    int v = (i < n) ? cnt[dir * N_NODES + i] : 0;
    int incl = block_incl_scan256(v, warpS);
    if (threadIdx.x == SCAN_B - 1) part[dir * NB_MAX + blockIdx.x] = incl;
}

__global__ void scan_top(int* __restrict__ part, int nb) {
    __shared__ int warpS[16];
    int dir = blockIdx.y;
    int lane = threadIdx.x & 31, w = threadIdx.x >> 5;
    int v = (threadIdx.x < nb) ? part[dir * NB_MAX + threadIdx.x] : 0;
    int incl = v;
#pragma unroll
    for (int o = 1; o < 32; o <<= 1) {
        int t = __shfl_up_sync(0xffffffffu, incl, o);
        if (lane >= o) incl += t;
    }
    if (lane == 31) warpS[w] = incl;
    __syncthreads();
    if (w == 0) {
        int s = (lane < 16) ? warpS[lane] : 0;
#pragma unroll
        for (int o = 1; o < 16; o <<= 1) {
            int t = __shfl_up_sync(0xffffffffu, s, o);
            if (lane >= o) s += t;
        }
        if (lane < 16) warpS[lane] = s;
    }
    __syncthreads();
    if (w > 0) incl += warpS[w - 1];
    if (threadIdx.x < nb) part[dir * NB_MAX + threadIdx.x] = incl - v;
}

__global__ void scan_write(const int* __restrict__ cnt, const int* __restrict__ part,
                           int* __restrict__ rowptr, int* __restrict__ cursor, int n, int E) {
    __shared__ int warpS[8];
    int dir = blockIdx.y;
    int i = blockIdx.x * SCAN_B + threadIdx.x;
    int v = (i < n) ? cnt[dir * N_NODES + i] : 0;
    int incl = block_incl_scan256(v, warpS);
    int ex = incl - v + part[dir * NB_MAX + blockIdx.x];
    if (i < n) {
        rowptr[dir * (N_NODES + 1) + i] = ex;
        cursor[dir * N_NODES + i] = ex;
        if (i == n - 1) rowptr[dir * (N_NODES + 1) + n] = E;
    }
}

__global__ void scatter_adj(const int* __restrict__ src, const int* __restrict__ dst,
                            int* __restrict__ cursor, int* __restrict__ adj, int E) {
    int e = blockIdx.x * blockDim.x + threadIdx.x;
    if (e < E) {
        int s = src[e], d = dst[e];
        int p0 = atomicAdd(&cursor[s], 1);
        adj[p0] = d;
        int p1 = atomicAdd(&cursor[N_NODES + d], 1);
        adj[E_MAX + p1] = s;
    }
}

// ---------------- CSR aggregation: one warp per node, no atomics ----------------
__global__ __launch_bounds__(256) void aggregate_csr(
    const float* __restrict__ x, const int* __restrict__ rowptr,
    const int* __restrict__ adj, float* __restrict__ agg, int Nn, int D)
{
    int node = blockIdx.x * 8 + (threadIdx.x >> 5);
    if (node >= Nn) return;
    int lane = threadIdx.x & 31;
    int p0 = __ldg(&rowptr[node]);
    int p1 = __ldg(&rowptr[node + 1]);
    int deg = p1 - p0;
    float inv = 1.0f / (float)(deg > 0 ? deg : 1);
    const bool wide = (D > 128);

    float4 a0 = make_float4(0.f, 0.f, 0.f, 0.f);
    float4 a1 = make_float4(0.f, 0.f, 0.f, 0.f);

    int p = p0;
    for (; p + 1 < p1; p += 2) {
        int g0 = __ldg(&adj[p]);
        int g1 = __ldg(&adj[p + 1]);
        const float4* r0 = (const float4*)(x + (size_t)g0 * D);
        const float4* r1 = (const float4*)(x + (size_t)g1 * D);
        float4 v0 = __ldg(&r0[lane]);
        float4 v1 = __ldg(&r1[lane]);
        a0.x += v0.x + v1.x; a0.y += v0.y + v1.y;
        a0.z += v0.z + v1.z; a0.w += v0.w + v1.w;
        if (wide) {
            float4 w0 = __ldg(&r0[lane + 32]);
            float4 w1 = __ldg(&r1[lane + 32]);
            a1.x += w0.x + w1.x; a1.y += w0.y + w1.y;
            a1.z += w0.z + w1.z; a1.w += w0.w + w1.w;
        }
    }
    if (p < p1) {
        int g0 = __ldg(&adj[p]);
        const float4* r0 = (const float4*)(x + (size_t)g0 * D);
        float4 v0 = __ldg(&r0[lane]);
        a0.x += v0.x; a0.y += v0.y; a0.z += v0.z; a0.w += v0.w;
        if (wide) {
            float4 w0 = __ldg(&r0[lane + 32]);
            a1.x += w0.x; a1.y += w0.y; a1.z += w0.z; a1.w += w0.w;
        }
    }

    float4* op = (float4*)(agg + (size_t)node * D);
    a0.x *= inv; a0.y *= inv; a0.z *= inv; a0.w *= inv;
    op[lane] = a0;
    if (wide) {
        a1.x *= inv; a1.y *= inv; a1.z *= inv; a1.w *= inv;
        op[lane + 32] = a1;
    }
}

// ---------------------------------------------------------------------------
// TF32 tensor-core fused dual GEMM + bias + ReLU
// ---------------------------------------------------------------------------
#define BM 128
#define BN 128
#define BK 8
#define AS_STR 132
#define BS_STR 12

__global__ __launch_bounds__(256) void sage_gemm_tf32(
    const float* __restrict__ Aagg, const float* __restrict__ Ax,
    const float* __restrict__ Wl, const float* __restrict__ Wr,
    const float* __restrict__ bias, float* __restrict__ out,
    int M, int K)
{
    __shared__ unsigned As[2][BK][AS_STR];
    __shared__ unsigned Bs[2][BN][BS_STR];

    const int tid  = threadIdx.x;
    const int lane = tid & 31;
    const int warp = tid >> 5;
    const int wm = (warp & 1) * 64;
    const int wn = (warp >> 1) * 32;
    const int bm = blockIdx.x * BM;
    const int bn = blockIdx.y * BN;

    float acc[4][4][4];
#pragma unroll
    for (int mi = 0; mi < 4; ++mi)
#pragma unroll
        for (int ni = 0; ni < 4; ++ni)
#pragma unroll
            for (int c = 0; c < 4; ++c) acc[mi][ni][c] = 0.f;

    const int arow  = tid >> 1;
    const int akoff = (tid & 1) << 2;
    const int bkrow = tid >> 5;
    const int bn4   = (tid & 31) << 2;
    const bool avalid = (bm + arow) < M;

    const int K2 = 2 * K;

    {
        float4 av = make_float4(0.f, 0.f, 0.f, 0.f);
        if (avalid) av = *(const float4*)(Aagg + (size_t)(bm + arow) * K + akoff);
        float4 bv = *(const float4*)(Wl + (size_t)bkrow * HID + bn + bn4);
        As[0][akoff + 0][arow] = f2tf32(av.x);
        As[0][akoff + 1][arow] = f2tf32(av.y);
        As[0][akoff + 2][arow] = f2tf32(av.z);
        As[0][akoff + 3][arow] = f2tf32(av.w);
        Bs[0][bn4 + 0][bkrow] = f2tf32(bv.x);
        Bs[0][bn4 + 1][bkrow] = f2tf32(bv.y);
        Bs[0][bn4 + 2][bkrow] = f2tf32(bv.z);
        Bs[0][bn4 + 3][bkrow] = f2tf32(bv.w);
    }
    __syncthreads();

    int s = 0;
    for (int kt = 0; kt < K2; kt += BK) {
        const int nkt = kt + BK;
        const bool has_next = nkt < K2;
        float4 av2, bv2;
        if (has_next) {
            const float* A; const float* B; int k0;
            if (nkt < K) { A = Aagg; B = Wl; k0 = nkt; }
            else         { A = Ax;   B = Wr; k0 = nkt - K; }
            av2 = make_float4(0.f, 0.f, 0.f, 0.f);
            if (avalid) av2 = *(const float4*)(A + (size_t)(bm + arow) * K + k0 + akoff);
            bv2 = *(const float4*)(B + (size_t)(k0 + bkrow) * HID + bn + bn4);
        }

        unsigned a[4][4], b[4][2];
        const int qk = lane & 3;
        const int qr = lane >> 2;
#pragma unroll
        for (int mi = 0; mi < 4; ++mi) {
            int m0 = wm + mi * 16 + qr;
            a[mi][0] = As[s][qk][m0];
            a[mi][1] = As[s][qk][m0 + 8];
            a[mi][2] = As[s][qk + 4][m0];
            a[mi][3] = As[s][qk + 4][m0 + 8];
        }
#pragma unroll
        for (int ni = 0; ni < 4; ++ni) {
            int n0 = wn + ni * 8 + qr;
            b[ni][0] = Bs[s][n0][qk];
            b[ni][1] = Bs[s][n0][qk + 4];
        }
#pragma unroll
        for (int mi = 0; mi < 4; ++mi)
#pragma unroll
            for (int ni = 0; ni < 4; ++ni)
                mma1688(acc[mi][ni], a[mi], b[ni]);

        if (has_next) {
            int t = s ^ 1;
            As[t][akoff + 0][arow] = f2tf32(av2.x);
            As[t][akoff + 1][arow] = f2tf32(av2.y);
            As[t][akoff + 2][arow] = f2tf32(av2.z);
            As[t][akoff + 3][arow] = f2tf32(av2.w);
            Bs[t][bn4 + 0][bkrow] = f2tf32(bv2.x);
            Bs[t][bn4 + 1][bkrow] = f2tf32(bv2.y);
            Bs[t][bn4 + 2][bkrow] = f2tf32(bv2.z);
            Bs[t][bn4 + 3][bkrow] = f2tf32(bv2.w);
        }
        __syncthreads();
        s ^= 1;
    }

    const int qk = lane & 3;
    const int qr = lane >> 2;
#pragma unroll
    for (int mi = 0; mi < 4; ++mi) {
        int r0 = bm + wm + mi * 16 + qr;
#pragma unroll
        for (int ni = 0; ni < 4; ++ni) {
            int c0 = bn + wn + ni * 8 + qk * 2;
            float bb0 = bias[c0];
            float bb1 = bias[c0 + 1];
            if (r0 < M) {
                float2 v;
                v.x = fmaxf(acc[mi][ni][0] + bb0, 0.f);
                v.y = fmaxf(acc[mi][ni][1] + bb1, 0.f);
                *(float2*)(out + (size_t)r0 * HID + c0) = v;
            }
            if (r0 + 8 < M) {
                float2 v;
                v.x = fmaxf(acc[mi][ni][2] + bb0, 0.f);
                v.y = fmaxf(acc[mi][ni][3] + bb1, 0.f);
                *(float2*)(out + (size_t)(r0 + 8) * HID + c0) = v;
            }
        }
    }
}

extern "C" void kernel_launch(void* const* d_in, const int* in_sizes, int n_in,
                              void* d_out, int out_size)
{
    const float* x_human = (const float*)d_in[0];
    const float* x_bact  = (const float*)d_in[1];
    const int*   ei      = (const int*)d_in[2];
    const float* h1_Wl = (const float*)d_in[3];
    const float* h1_Wr = (const float*)d_in[4];
    const float* h1_b  = (const float*)d_in[5];
    const float* h2_Wl = (const float*)d_in[6];
    const float* h2_Wr = (const float*)d_in[7];
    const float* h2_b  = (const float*)d_in[8];
    const float* b1_Wl = (const float*)d_in[9];
    const float* b1_Wr = (const float*)d_in[10];
    const float* b1_b  = (const float*)d_in[11];
    const float* b2_Wl = (const float*)d_in[12];
    const float* b2_Wr = (const float*)d_in[13];
    const float* b2_b  = (const float*)d_in[14];

    const int N = in_sizes[0] / DIN;      // 100000
    const int E = in_sizes[2] / 2;        // 1600000
    const int* src = ei;
    const int* dst = ei + E;

    float* out  = (float*)d_out;
    float* hout = out;
    float* bout = out + (size_t)N * HID;

    float *agg, *hid, *agg2, *hid2;
    int *cnt, *part, *rowptr, *cursor, *adj;
    cudaGetSymbolAddress((void**)&agg,    g_agg);
    cudaGetSymbolAddress((void**)&hid,    g_hid);
    cudaGetSymbolAddress((void**)&agg2,   g_agg2);
    cudaGetSymbolAddress((void**)&hid2,   g_hid2);
    cudaGetSymbolAddress((void**)&cnt,    g_cnt);
    cudaGetSymbolAddress((void**)&part,   g_part);
    cudaGetSymbolAddress((void**)&rowptr, g_rowptr);
    cudaGetSymbolAddress((void**)&cursor, g_cursor);
    cudaGetSymbolAddress((void**)&adj,    g_adj);

    const int* rp_s = rowptr;
    const int* rp_d = rowptr + (N_NODES + 1);
    const int* adj_s = adj;
    const int* adj_d = adj + E_MAX;

    const int TB = 256;
    const int nb_N = (N + TB - 1) / TB;
    const int nb_E = (E + TB - 1) / TB;
    const int nb_agg = (N * 32 + TB - 1) / TB;
    dim3 gemm_grid((N + 127) / 128, 2);
    dim3 scan_grid(nb_N, 2);
    dim3 top_grid(1, 2);

    // ---- CSR build (capture/default stream) ----
    cudaMemsetAsync(cnt, 0, 2 * N_NODES * sizeof(int));
    count_deg<<<nb_E, TB>>>(src, dst, cnt, E);
    scan_reduce<<<scan_grid, TB>>>(cnt, part, N);
    scan_top<<<top_grid, 512>>>(part, nb_N);
    scan_write<<<scan_grid, TB>>>(cnt, part, rowptr, cursor, N, E);
    scatter_adj<<<nb_E, TB>>>(src, dst, cursor, adj, E);

    const bool par = g_par_ok;
    cudaStream_t sb = par ? g_s1 : (cudaStream_t)0;
    if (par) {
        cudaEventRecord(g_ev_fork, 0);
        cudaStreamWaitEvent(g_s1, g_ev_fork, 0);
    }

    // ---- human branch (default stream): by-src CSR gathers dst rows ----
    aggregate_csr<<<nb_agg, TB>>>(x_human, rp_s, adj_s, agg, N, DIN);
    sage_gemm_tf32<<<gemm_grid, TB>>>(agg, x_human, h1_Wl, h1_Wr, h1_b, hid, N, DIN);
    aggregate_csr<<<nb_agg, TB>>>(hid, rp_s, adj_s, agg, N, HID);
    sage_gemm_tf32<<<gemm_grid, TB>>>(agg, hid, h2_Wl, h2_Wr, h2_b, hout, N, HID);

    // ---- bacterial branch (second stream): by-dst CSR gathers src rows ----
    aggregate_csr<<<nb_agg, TB, 0, sb>>>(x_bact, rp_d, adj_d, agg2, N, DIN);
    sage_gemm_tf32<<<gemm_grid, TB, 0, sb>>>(agg2, x_bact, b1_Wl, b1_Wr, b1_b, hid2, N, DIN);
    aggregate_csr<<<nb_agg, TB, 0, sb>>>(hid2, rp_d, adj_d, agg2, N, HID);
    sage_gemm_tf32<<<gemm_grid, TB, 0, sb>>>(agg2, hid2, b2_Wl, b2_Wr, b2_b, bout, N, HID);

    if (par) {
        cudaEventRecord(g_ev_join, g_s1);
        cudaStreamWaitEvent((cudaStream_t)0, g_ev_join, 0);
    }
}

// round 8
// speedup vs baseline: 3.3565x; 1.6772x over previous
#include <cuda_runtime.h>
#include <cuda_bf16.h>
#include <cstdint>

#define N_NODES 100000
#define HID 256
#define DIN 128
#define E_MAX 1600000
#define SCAN_B 256
#define NB_MAX 512

// ---------------- scratch (no cudaMalloc allowed) ----------------
__device__ float g_agg [(size_t)N_NODES * HID];   // human branch agg (tf32-rounded)
__device__ float g_hid [(size_t)N_NODES * HID];   // human branch layer-1 act (tf32)
__device__ float g_agg2[(size_t)N_NODES * HID];   // bacterial agg
__device__ float g_hid2[(size_t)N_NODES * HID];   // bacterial layer-1 act
__device__ float g_xh_t[(size_t)N_NODES * DIN];   // x_human tf32-rounded
__device__ float g_xb_t[(size_t)N_NODES * DIN];   // x_bact tf32-rounded
__device__ float g_wt[393216];                    // 8 weight matrices, tf32-rounded
__device__ int   g_cnt[2 * N_NODES];
__device__ int   g_part[2 * NB_MAX];
__device__ int   g_rowptr[2 * (N_NODES + 1)];
__device__ int   g_cursor[2 * N_NODES];
__device__ int   g_adj[2 * E_MAX];

// weight scratch offsets (floats)
#define W_H1L 0
#define W_H1R 32768
#define W_H2L 65536
#define W_H2R 131072
#define W_B1L 196608
#define W_B1R 229376
#define W_B2L 262144
#define W_B2R 327680

// ---------------- tf32 helpers ----------------
__device__ __forceinline__ unsigned f2tf32(float f) {
    unsigned u;
    asm("cvt.rna.tf32.f32 %0, %1;" : "=r"(u) : "f"(f));
    return u;
}
__device__ __forceinline__ float t32(float f) { return __uint_as_float(f2tf32(f)); }

__device__ __forceinline__ void mma1688(float* c, const unsigned* a, const unsigned* b) {
    asm volatile(
        "mma.sync.aligned.m16n8k8.row.col.f32.tf32.tf32.f32 "
        "{%0,%1,%2,%3}, {%4,%5,%6,%7}, {%8,%9}, {%0,%1,%2,%3};"
        : "+f"(c[0]), "+f"(c[1]), "+f"(c[2]), "+f"(c[3])
        : "r"(a[0]), "r"(a[1]), "r"(a[2]), "r"(a[3]),
          "r"(b[0]), "r"(b[1]));
}

__device__ __forceinline__ void cp16(uint32_t smem, const void* gmem, int bytes) {
    asm volatile("cp.async.ca.shared.global [%0], [%1], 16, %2;"
                 :: "r"(smem), "l"(gmem), "r"(bytes) : "memory");
}
__device__ __forceinline__ void cp_commit() {
    asm volatile("cp.async.commit_group;" ::: "memory");
}
template <int NN>
__device__ __forceinline__ void cp_wait() {
    asm volatile("cp.async.wait_group %0;" :: "n"(NN) : "memory");
}

// ---------------- GEMM geometry ----------------
#define BM 128
#define BN 128
#define BK 16
#define AST 20            // As row stride (floats): (20*m + k) % 32 conflict-free
#define BST 136           // Bs row stride (floats): 136 % 32 == 8 -> conflict-free
#define STAGES 4
#define STG_FLTS (BM * AST + BK * BST)   // 2560 + 2176 = 4736 floats
#define GEMM_SMEM (STAGES * STG_FLTS * 4)

// ---------------- one-time resources ----------------
__global__ void sage_gemm_pipe(const float*, const float*, const float*, const float*,
                               const float*, float*, int, int, int);

static cudaStream_t g_s1;
static cudaEvent_t  g_ev_fork, g_ev_join;
static bool g_par_ok = false;
namespace {
struct _Init {
    _Init() {
        bool ok = true;
        ok = ok && (cudaStreamCreateWithFlags(&g_s1, cudaStreamNonBlocking) == cudaSuccess);
        ok = ok && (cudaEventCreateWithFlags(&g_ev_fork, cudaEventDisableTiming) == cudaSuccess);
        ok = ok && (cudaEventCreateWithFlags(&g_ev_join, cudaEventDisableTiming) == cudaSuccess);
        g_par_ok = ok;
        cudaFuncSetAttribute(sage_gemm_pipe, cudaFuncAttributeMaxDynamicSharedMemorySize, GEMM_SMEM);
    }
};
static _Init _init;
}

// ---------------- small conversion kernels ----------------
__global__ void cvt_tf32_k(const float* __restrict__ in, float* __restrict__ outp, int n) {
    int i = blockIdx.x * blockDim.x + threadIdx.x;
    int stride = gridDim.x * blockDim.x;
    for (; i < n; i += stride) outp[i] = t32(in[i]);
}

// ---------------- CSR build ----------------
__global__ void count_deg(const int* __restrict__ src, const int* __restrict__ dst,
                          int* __restrict__ cnt, int E) {
    int e = blockIdx.x * blockDim.x + threadIdx.x;
    if (e < E) {
        atomicAdd(&cnt[src[e]], 1);
        atomicAdd(&cnt[N_NODES + dst[e]], 1);
    }
}

__device__ __forceinline__ int block_incl_scan256(int v, int* warpS) {
    int lane = threadIdx.x & 31, w = threadIdx.x >> 5;
#pragma unroll
    for (int o = 1; o < 32; o <<= 1) {
        int t = __shfl_up_sync(0xffffffffu, v, o);
        if (lane >= o) v += t;
    }
    if (lane == 31) warpS[w] = v;
    __syncthreads();
    if (w == 0) {
        int s = (lane < 8) ? warpS[lane] : 0;
#pragma unroll
        for (int o = 1; o < 8; o <<= 1) {
            int t = __shfl_up_sync(0xffffffffu, s, o);
            if (lane >= o) s += t;
        }
        if (lane < 8) warpS[lane] = s;
    }
    __syncthreads();
    int add = (w > 0) ? warpS[w - 1] : 0;
    return v + add;
}

__global__ void scan_reduce(const int* __restrict__ cnt, int* __restrict__ part, int n) {
    __shared__ int warpS[8];
    int dir = blockIdx.y;
    int i = blockIdx.x * SCAN_B + threadIdx.x;
    int v = (i < n) ? cnt[dir * N_NODES + i] : 0;
    int incl = block_incl_scan256(v, warpS);
    if (threadIdx.x == SCAN_B - 1) part[dir * NB_MAX + blockIdx.x] = incl;
}

__global__ void scan_top(int* __restrict__ part, int nb) {
    __shared__ int warpS[16];
    int dir = blockIdx.y;
    int lane = threadIdx.x & 31, w = threadIdx.x >> 5;
    int v = (threadIdx.x < nb) ? part[dir * NB_MAX + threadIdx.x] : 0;
    int incl = v;
#pragma unroll
    for (int o = 1; o < 32; o <<= 1) {
        int t = __shfl_up_sync(0xffffffffu, incl, o);
        if (lane >= o) incl += t;
    }
    if (lane == 31) warpS[w] = incl;
    __syncthreads();
    if (w == 0) {
        int s = (lane < 16) ? warpS[lane] : 0;
#pragma unroll
        for (int o = 1; o < 16; o <<= 1) {
            int t = __shfl_up_sync(0xffffffffu, s, o);
            if (lane >= o) s += t;
        }
        if (lane < 16) warpS[lane] = s;
    }
    __syncthreads();
    if (w > 0) incl += warpS[w - 1];
    if (threadIdx.x < nb) part[dir * NB_MAX + threadIdx.x] = incl - v;
}

__global__ void scan_write(const int* __restrict__ cnt, const int* __restrict__ part,
                           int* __restrict__ rowptr, int* __restrict__ cursor, int n, int E) {
    __shared__ int warpS[8];
    int dir = blockIdx.y;
    int i = blockIdx.x * SCAN_B + threadIdx.x;
    int v = (i < n) ? cnt[dir * N_NODES + i] : 0;
    int incl = block_incl_scan256(v, warpS);
    int ex = incl - v + part[dir * NB_MAX + blockIdx.x];
    if (i < n) {
        rowptr[dir * (N_NODES + 1) + i] = ex;
        cursor[dir * N_NODES + i] = ex;
        if (i == n - 1) rowptr[dir * (N_NODES + 1) + n] = E;
    }
}

__global__ void scatter_adj(const int* __restrict__ src, const int* __restrict__ dst,
                            int* __restrict__ cursor, int* __restrict__ adj, int E) {
    int e = blockIdx.x * blockDim.x + threadIdx.x;
    if (e < E) {
        int s = src[e], d = dst[e];
        int p0 = atomicAdd(&cursor[s], 1);
        adj[p0] = d;
        int p1 = atomicAdd(&cursor[N_NODES + d], 1);
        adj[E_MAX + p1] = s;
    }
}

// ---------------- CSR aggregation (tf32-rounded output) ----------------
__global__ __launch_bounds__(256) void aggregate_csr(
    const float* __restrict__ x, const int* __restrict__ rowptr,
    const int* __restrict__ adj, float* __restrict__ agg, int Nn, int D)
{
    int node = blockIdx.x * 8 + (threadIdx.x >> 5);
    if (node >= Nn) return;
    int lane = threadIdx.x & 31;
    int p0 = __ldg(&rowptr[node]);
    int p1 = __ldg(&rowptr[node + 1]);
    int deg = p1 - p0;
    float inv = 1.0f / (float)(deg > 0 ? deg : 1);
    const bool wide = (D > 128);

    float4 a0 = make_float4(0.f, 0.f, 0.f, 0.f);
    float4 a1 = make_float4(0.f, 0.f, 0.f, 0.f);

    int p = p0;
    for (; p + 1 < p1; p += 2) {
        int g0 = __ldg(&adj[p]);
        int g1 = __ldg(&adj[p + 1]);
        const float4* r0 = (const float4*)(x + (size_t)g0 * D);
        const float4* r1 = (const float4*)(x + (size_t)g1 * D);
        float4 v0 = __ldg(&r0[lane]);
        float4 v1 = __ldg(&r1[lane]);
        a0.x += v0.x + v1.x; a0.y += v0.y + v1.y;
        a0.z += v0.z + v1.z; a0.w += v0.w + v1.w;
        if (wide) {
            float4 w0 = __ldg(&r0[lane + 32]);
            float4 w1 = __ldg(&r1[lane + 32]);
            a1.x += w0.x + w1.x; a1.y += w0.y + w1.y;
            a1.z += w0.z + w1.z; a1.w += w0.w + w1.w;
        }
    }
    if (p < p1) {
        int g0 = __ldg(&adj[p]);
        const float4* r0 = (const float4*)(x + (size_t)g0 * D);
        float4 v0 = __ldg(&r0[lane]);
        a0.x += v0.x; a0.y += v0.y; a0.z += v0.z; a0.w += v0.w;
        if (wide) {
            float4 w0 = __ldg(&r0[lane + 32]);
            a1.x += w0.x; a1.y += w0.y; a1.z += w0.z; a1.w += w0.w;
        }
    }

    float4* op = (float4*)(agg + (size_t)node * D);
    a0.x = t32(a0.x * inv); a0.y = t32(a0.y * inv);
    a0.z = t32(a0.z * inv); a0.w = t32(a0.w * inv);
    op[lane] = a0;
    if (wide) {
        a1.x = t32(a1.x * inv); a1.y = t32(a1.y * inv);
        a1.z = t32(a1.z * inv); a1.w = t32(a1.w * inv);
        op[lane + 32] = a1;
    }
}

// ---------------------------------------------------------------------------
// cp.async pipelined tf32 GEMM. Inputs already tf32-rounded fp32 bits.
//   out[i,:] = relu( Aagg[i,:K]@Wl + Ax[i,:K]@Wr + b ), optional tf32 round on store
// ---------------------------------------------------------------------------
__global__ __launch_bounds__(256, 2) void sage_gemm_pipe(
    const float* __restrict__ Aagg, const float* __restrict__ Ax,
    const float* __restrict__ Wl, const float* __restrict__ Wr,
    const float* __restrict__ bias, float* __restrict__ out,
    int M, int K, int cvt_out)
{
    extern __shared__ float smem[];
    const int tid  = threadIdx.x;
    const int lane = tid & 31;
    const int warp = tid >> 5;
    const int wm = (warp & 1) * 64;
    const int wn = (warp >> 1) * 32;
    const int bm = blockIdx.x * BM;
    const int bn = blockIdx.y * BN;

    uint32_t smem_u32;
    {
        uint32_t a;
        asm("{ .reg .u64 t; cvta.to.shared.u64 t, %1; cvt.u32.u64 %0, t; }"
            : "=r"(a) : "l"(smem));
        smem_u32 = a;
    }

    float acc[4][4][4];
#pragma unroll
    for (int mi = 0; mi < 4; ++mi)
#pragma unroll
        for (int ni = 0; ni < 4; ++ni)
#pragma unroll
            for (int c = 0; c < 4; ++c) acc[mi][ni][c] = 0.f;

    const int ntiles = (2 * K) / BK;

    // per-thread cp.async source geometry
    const int ar0 = tid >> 2;                 // A rows handled: ar0, ar0+64
    const int ak0 = (tid & 3) << 2;           // k offset 0/4/8/12
    const int bk0 = tid >> 5;                 // B k rows: bk0, bk0+8
    const int bn0 = (tid & 31) << 2;          // n offset

    auto load_tile = [&](int stage, int tile) {
        int kt = tile * BK;
        const float* A; const float* B; int k0;
        if (kt < K) { A = Aagg; B = Wl; k0 = kt; }
        else        { A = Ax;   B = Wr; k0 = kt - K; }
        uint32_t as_base = smem_u32 + (stage * STG_FLTS) * 4;
        uint32_t bs_base = as_base + (BM * AST) * 4;
#pragma unroll
        for (int r = 0; r < 2; ++r) {
            int row = ar0 + r * 64;
            uint32_t d = as_base + (row * AST + ak0) * 4;
            const float* s = A + (size_t)(bm + row) * K + k0 + ak0;
            cp16(d, s, (bm + row) < M ? 16 : 0);
        }
#pragma unroll
        for (int r = 0; r < 2; ++r) {
            int kr = bk0 + r * 8;
            uint32_t d = bs_base + (kr * BST + bn0) * 4;
            const float* s = B + (size_t)(k0 + kr) * HID + bn + bn0;
            cp16(d, s, 16);
        }
    };

    // prologue: stages 0..STAGES-2
#pragma unroll
    for (int s = 0; s < STAGES - 1; ++s) {
        load_tile(s, s);
        cp_commit();
    }
    cp_wait<STAGES - 2>();
    __syncthreads();

    const int qk = lane & 3;
    const int qr = lane >> 2;

    for (int t = 0; t < ntiles; ++t) {
        int stage = t % STAGES;
        const float* as = smem + stage * STG_FLTS;
        const float* bs = as + BM * AST;

#pragma unroll
        for (int kg = 0; kg < BK; kg += 8) {
            unsigned a[4][4], b[4][2];
#pragma unroll
            for (int mi = 0; mi < 4; ++mi) {
                int m0 = wm + mi * 16 + qr;
                a[mi][0] = __float_as_uint(as[m0 * AST + kg + qk]);
                a[mi][1] = __float_as_uint(as[(m0 + 8) * AST + kg + qk]);
                a[mi][2] = __float_as_uint(as[m0 * AST + kg + qk + 4]);
                a[mi][3] = __float_as_uint(as[(m0 + 8) * AST + kg + qk + 4]);
            }
#pragma unroll
            for (int ni = 0; ni < 4; ++ni) {
                int n0 = wn + ni * 8 + qr;
                b[ni][0] = __float_as_uint(bs[(kg + qk) * BST + n0]);
                b[ni][1] = __float_as_uint(bs[(kg + qk + 4) * BST + n0]);
            }
#pragma unroll
            for (int mi = 0; mi < 4; ++mi)
#pragma unroll
                for (int ni = 0; ni < 4; ++ni)
                    mma1688(acc[mi][ni], a[mi], b[ni]);
        }

        int nt = t + STAGES - 1;
        if (nt < ntiles) load_tile(nt % STAGES, nt);
        cp_commit();
        cp_wait<STAGES - 2>();
        __syncthreads();
    }

    // epilogue
#pragma unroll
    for (int mi = 0; mi < 4; ++mi) {
        int r0 = bm + wm + mi * 16 + qr;
#pragma unroll
        for (int ni = 0; ni < 4; ++ni) {
            int c0 = bn + wn + ni * 8 + qk * 2;
            float bb0 = bias[c0];
            float bb1 = bias[c0 + 1];
            if (r0 < M) {
                float2 v;
                v.x = fmaxf(acc[mi][ni][0] + bb0, 0.f);
                v.y = fmaxf(acc[mi][ni][1] + bb1, 0.f);
                if (cvt_out) { v.x = t32(v.x); v.y = t32(v.y); }
                *(float2*)(out + (size_t)r0 * HID + c0) = v;
            }
            if (r0 + 8 < M) {
                float2 v;
                v.x = fmaxf(acc[mi][ni][2] + bb0, 0.f);
                v.y = fmaxf(acc[mi][ni][3] + bb1, 0.f);
                if (cvt_out) { v.x = t32(v.x); v.y = t32(v.y); }
                *(float2*)(out + (size_t)(r0 + 8) * HID + c0) = v;
            }
        }
    }
}

extern "C" void kernel_launch(void* const* d_in, const int* in_sizes, int n_in,
                              void* d_out, int out_size)
{
    const float* x_human = (const float*)d_in[0];
    const float* x_bact  = (const float*)d_in[1];
    const int*   ei      = (const int*)d_in[2];
    const float* h1_Wl = (const float*)d_in[3];
    const float* h1_Wr = (const float*)d_in[4];
    const float* h1_b  = (const float*)d_in[5];
    const float* h2_Wl = (const float*)d_in[6];
    const float* h2_Wr = (const float*)d_in[7];
    const float* h2_b  = (const float*)d_in[8];
    const float* b1_Wl = (const float*)d_in[9];
    const float* b1_Wr = (const float*)d_in[10];
    const float* b1_b  = (const float*)d_in[11];
    const float* b2_Wl = (const float*)d_in[12];
    const float* b2_Wr = (const float*)d_in[13];
    const float* b2_b  = (const float*)d_in[14];

    const int N = in_sizes[0] / DIN;      // 100000
    const int E = in_sizes[2] / 2;        // 1600000
    const int* src = ei;
    const int* dst = ei + E;

    float* out  = (float*)d_out;
    float* hout = out;
    float* bout = out + (size_t)N * HID;

    float *agg, *hid, *agg2, *hid2, *xh, *xb, *wt;
    int *cnt, *part, *rowptr, *cursor, *adj;
    cudaGetSymbolAddress((void**)&agg,    g_agg);
    cudaGetSymbolAddress((void**)&hid,    g_hid);
    cudaGetSymbolAddress((void**)&agg2,   g_agg2);
    cudaGetSymbolAddress((void**)&hid2,   g_hid2);
    cudaGetSymbolAddress((void**)&xh,     g_xh_t);
    cudaGetSymbolAddress((void**)&xb,     g_xb_t);
    cudaGetSymbolAddress((void**)&wt,     g_wt);
    cudaGetSymbolAddress((void**)&cnt,    g_cnt);
    cudaGetSymbolAddress((void**)&part,   g_part);
    cudaGetSymbolAddress((void**)&rowptr, g_rowptr);
    cudaGetSymbolAddress((void**)&cursor, g_cursor);
    cudaGetSymbolAddress((void**)&adj,    g_adj);

    const int* rp_s = rowptr;
    const int* rp_d = rowptr + (N_NODES + 1);
    const int* adj_s = adj;
    const int* adj_d = adj + E_MAX;

    const int TB = 256;
    const int nb_N = (N + TB - 1) / TB;
    const int nb_E = (E + TB - 1) / TB;
    const int nb_agg = (N * 32 + TB - 1) / TB;
    dim3 gemm_grid((N + 127) / 128, 2);
    dim3 scan_grid(nb_N, 2);
    dim3 top_grid(1, 2);

    // ---- CSR build (default stream) ----
    cudaMemsetAsync(cnt, 0, 2 * N_NODES * sizeof(int));
    count_deg<<<nb_E, TB>>>(src, dst, cnt, E);
    scan_reduce<<<scan_grid, TB>>>(cnt, part, N);
    scan_top<<<top_grid, 512>>>(part, nb_N);
    scan_write<<<scan_grid, TB>>>(cnt, part, rowptr, cursor, N, E);
    scatter_adj<<<nb_E, TB>>>(src, dst, cursor, adj, E);

    const bool par = g_par_ok;
    cudaStream_t sb = par ? g_s1 : (cudaStream_t)0;
    if (par) {
        cudaEventRecord(g_ev_fork, 0);
        cudaStreamWaitEvent(g_s1, g_ev_fork, 0);
    }

    // ---- human branch (default stream) ----
    cvt_tf32_k<<<1024, TB>>>(x_human, xh, N * DIN);
    cvt_tf32_k<<<64, TB>>>(h1_Wl, wt + W_H1L, DIN * HID);
    cvt_tf32_k<<<64, TB>>>(h1_Wr, wt + W_H1R, DIN * HID);
    cvt_tf32_k<<<64, TB>>>(h2_Wl, wt + W_H2L, HID * HID);
    cvt_tf32_k<<<64, TB>>>(h2_Wr, wt + W_H2R, HID * HID);
    aggregate_csr<<<nb_agg, TB>>>(xh, rp_s, adj_s, agg, N, DIN);
    sage_gemm_pipe<<<gemm_grid, TB, GEMM_SMEM>>>(agg, xh, wt + W_H1L, wt + W_H1R, h1_b, hid, N, DIN, 1);
    aggregate_csr<<<nb_agg, TB>>>(hid, rp_s, adj_s, agg, N, HID);
    sage_gemm_pipe<<<gemm_grid, TB, GEMM_SMEM>>>(agg, hid, wt + W_H2L, wt + W_H2R, h2_b, hout, N, HID, 0);

    // ---- bacterial branch (second stream) ----
    cvt_tf32_k<<<1024, TB, 0, sb>>>(x_bact, xb, N * DIN);
    cvt_tf32_k<<<64, TB, 0, sb>>>(b1_Wl, wt + W_B1L, DIN * HID);
    cvt_tf32_k<<<64, TB, 0, sb>>>(b1_Wr, wt + W_B1R, DIN * HID);
    cvt_tf32_k<<<64, TB, 0, sb>>>(b2_Wl, wt + W_B2L, HID * HID);
    cvt_tf32_k<<<64, TB, 0, sb>>>(b2_Wr, wt + W_B2R, HID * HID);
    aggregate_csr<<<nb_agg, TB, 0, sb>>>(xb, rp_d, adj_d, agg2, N, DIN);
    sage_gemm_pipe<<<gemm_grid, TB, GEMM_SMEM, sb>>>(agg2, xb, wt + W_B1L, wt + W_B1R, b1_b, hid2, N, DIN, 1);
    aggregate_csr<<<nb_agg, TB, 0, sb>>>(hid2, rp_d, adj_d, agg2, N, HID);
    sage_gemm_pipe<<<gemm_grid, TB, GEMM_SMEM, sb>>>(agg2, hid2, wt + W_B2L, wt + W_B2R, b2_b, bout, N, HID, 0);

    if (par) {
        cudaEventRecord(g_ev_join, g_s1);
        cudaStreamWaitEvent((cudaStream_t)0, g_ev_join, 0);
    }
}